// round 17
// baseline (speedup 1.0000x reference)
#include <cuda_runtime.h>
#include <cstdint>

// CSpace resonator bank as 1st-order complex IIR, split-scan over time slices.
// 1024 sequences x 25 slices of 1920 samples; warp per slice.
// kA grid = 3200 slice blocks + 1 table block (double ladder -> g_ctab for kC).
// kA: pairwise chunk folding (E256) for half the loop overhead.
// kC: fold entry + scan + FFMA2-packed reconstruction, streaming stores.

#define TT 48000
#define CC 64
#define BB 8
#define KLEN 24000
#define NSLICE 25
#define SLEN 1920
#define NITERS 15           // 15 * 128 = 1920
#define NSEQ (BB * CC * 2)  // 1024
#define NWORK (NSEQ * NSLICE) // 25600
#define WPB 8               // warps per block
#define NBLK (NWORK / WPB)  // 3200

__device__ float2 g_tot[NWORK];
// table layout (32 floats per channel):
// [0..7]  e^1..e^4 (re,im)
// [8..17] A_k = E4^(2^k), k=0..4  (E4,E8,E16,E32,E64)
// [18..19] E128   [20..21] E1920   [22..23] g
// [24..31] w0..w3  (w_k = g * e^(3-k))
__device__ float g_ctab[CC][32];

__device__ __forceinline__ void cmulD(double& ar, double& ai, double br, double bi) {
    double t = ar * br - ai * bi;
    ai = ar * bi + ai * br;
    ar = t;
}
__device__ __forceinline__ void cmulF(float& ar, float& ai, float br, float bi) {
    float t = ar * br - ai * bi;
    ai = ar * bi + ai * br;
    ar = t;
}

// ---- packed f32x2 helpers ----
__device__ __forceinline__ unsigned long long pk2(float lo, float hi) {
    unsigned long long r;
    asm("mov.b64 %0, {%1,%2};" : "=l"(r) : "f"(lo), "f"(hi));
    return r;
}
__device__ __forceinline__ void unpk2(unsigned long long v, float& lo, float& hi) {
    asm("mov.b64 {%0,%1}, %2;" : "=f"(lo), "=f"(hi) : "l"(v));
}
__device__ __forceinline__ unsigned long long ffma2(unsigned long long a,
                                                    unsigned long long b,
                                                    unsigned long long c) {
    unsigned long long d;
    asm("fma.rn.f32x2 %0, %1, %2, %3;" : "=l"(d) : "l"(a), "l"(b), "l"(c));
    return d;
}

__device__ void make_tab_double(const float* __restrict__ kre,
                                const float* __restrict__ kim, int c)
{
    double k0r = kre[c * KLEN + 0], k0i = kim[c * KLEN + 0];
    double k1r = kre[c * KLEN + 1], k1i = kim[c * KLEN + 1];
    double inv = 1.0 / (k0r * k0r + k0i * k0i);
    double er = (k1r * k0r + k1i * k0i) * inv;
    double ei = (k1i * k0r - k1r * k0i) * inv;

    double e2r = er, e2i = ei;  cmulD(e2r, e2i, er, ei);
    double e3r = e2r, e3i = e2i; cmulD(e3r, e3i, er, ei);
    double e4r = e2r, e4i = e2i; cmulD(e4r, e4i, e2r, e2i);

    double Ar[6], Ai[6];
    Ar[0] = e4r; Ai[0] = e4i;
    #pragma unroll
    for (int k = 1; k < 6; ++k) { Ar[k] = Ar[k-1]; Ai[k] = Ai[k-1]; cmulD(Ar[k], Ai[k], Ar[k-1], Ai[k-1]); }
    double Cr[4], Ci[4];
    Cr[0] = Ar[5]; Ci[0] = Ai[5];
    #pragma unroll
    for (int k = 1; k < 4; ++k) { Cr[k] = Cr[k-1]; Ci[k] = Ci[k-1]; cmulD(Cr[k], Ci[k], Cr[k-1], Ci[k-1]); }
    double Fr = Cr[0], Fi = Ci[0];
    cmulD(Fr, Fi, Cr[1], Ci[1]);
    cmulD(Fr, Fi, Cr[2], Ci[2]);
    cmulD(Fr, Fi, Cr[3], Ci[3]);

    double w3r = k0r, w3i = k0i;
    double w2r = w3r, w2i = w3i; cmulD(w2r, w2i, er, ei);
    double w1r = w3r, w1i = w3i; cmulD(w1r, w1i, e2r, e2i);
    double w0r = w3r, w0i = w3i; cmulD(w0r, w0i, e3r, e3i);

    float* t = g_ctab[c];
    t[0] = (float)er;  t[1] = (float)ei;
    t[2] = (float)e2r; t[3] = (float)e2i;
    t[4] = (float)e3r; t[5] = (float)e3i;
    t[6] = (float)e4r; t[7] = (float)e4i;
    #pragma unroll
    for (int k = 0; k < 5; ++k) { t[8 + 2*k] = (float)Ar[k]; t[9 + 2*k] = (float)Ai[k]; }
    t[18] = (float)Ar[5]; t[19] = (float)Ai[5];
    t[20] = (float)Fr;    t[21] = (float)Fi;
    t[22] = (float)k0r;   t[23] = (float)k0i;
    t[24] = (float)w0r;   t[25] = (float)w0i;
    t[26] = (float)w1r;   t[27] = (float)w1i;
    t[28] = (float)w2r;   t[29] = (float)w2i;
    t[30] = (float)w3r;   t[31] = (float)w3i;
}

// ---------------- Kernel A: slice totals (pairwise fold) ----------------
template <bool REV>
__device__ __forceinline__ void sliceA(const float* __restrict__ x, int j, int lane,
                                       int c, int W,
                                       const float* __restrict__ kre,
                                       const float* __restrict__ kim)
{
    const unsigned FULL = 0xFFFFFFFFu;

    // derive constants in float (broadcast loads; no table dependency)
    float k0r = kre[c * KLEN + 0], k0i = kim[c * KLEN + 0];
    float k1r = kre[c * KLEN + 1], k1i = kim[c * KLEN + 1];
    float invd = 1.0f / (k0r * k0r + k0i * k0i);
    float er = (k1r * k0r + k1i * k0i) * invd;
    float ei = (k1i * k0r - k1r * k0i) * invd;

    float e2r = er, e2i = ei;   cmulF(e2r, e2i, er, ei);
    float e4r = e2r, e4i = e2i; cmulF(e4r, e4i, e2r, e2i);
    // A_k = E4^(2^k), k=0..4
    float Afr[5], Afi[5];
    Afr[0] = e4r; Afi[0] = e4i;
    #pragma unroll
    for (int k = 1; k < 5; ++k) { Afr[k] = Afr[k-1]; Afi[k] = Afi[k-1]; cmulF(Afr[k], Afi[k], Afr[k-1], Afi[k-1]); }
    float e128r = Afr[4], e128i = Afi[4]; cmulF(e128r, e128i, Afr[4], Afi[4]);
    float e256r = e128r,  e256i = e128i;  cmulF(e256r, e256i, e128r, e128i);
    // w_k = g * e^(3-k)
    float w3r = k0r, w3i = k0i;
    float w2r = w3r, w2i = w3i; cmulF(w2r, w2i, er, ei);
    float w1r = w2r, w1i = w2i; cmulF(w1r, w1i, er, ei);
    float w0r = w1r, w0i = w1i; cmulF(w0r, w0i, er, ei);

    auto loadY = [&](int i, float& yr, float& yi) {
        int n0 = j * SLEN + i * 128 + lane * 4;
        float4 v = REV ? *reinterpret_cast<const float4*>(x + (TT - 4 - n0))
                       : *reinterpret_cast<const float4*>(x + n0);
        float x0, x1, x2, x3;
        if (!REV) { x0=v.x; x1=v.y; x2=v.z; x3=v.w; }
        else      { x0=v.w; x1=v.z; x2=v.y; x3=v.x; }
        yr = w0r*x0 + w1r*x1 + w2r*x2 + w3r*x3;
        yi = w0i*x0 + w1i*x1 + w2i*x2 + w3i*x3;
    };

    // pairwise fold: A = E256*A + (y1 + E128*y0); leftover chunk 14
    float Acr = 0.f, Aci = 0.f;
    #pragma unroll
    for (int p = 0; p < 7; ++p) {
        float y0r, y0i, y1r, y1i;
        loadY(2*p,     y0r, y0i);
        loadY(2*p + 1, y1r, y1i);
        float ypr = y1r + e128r*y0r - e128i*y0i;
        float ypi = y1i + e128r*y0i + e128i*y0r;
        float nAr = ypr + e256r*Acr - e256i*Aci;
        float nAi = ypi + e256r*Aci + e256i*Acr;
        Acr = nAr; Aci = nAi;
    }
    {
        float yr, yi;
        loadY(14, yr, yi);
        float nAr = yr + e128r*Acr - e128i*Aci;
        float nAi = yi + e128r*Aci + e128i*Acr;
        Acr = nAr; Aci = nAi;
    }

    // weight = E4^(31-lane); one butterfly reduction of w*A
    float wr = 1.f, wi = 0.f;
    {
        int p = 31 - lane;
        #pragma unroll
        for (int k = 0; k < 5; ++k)
            if ((p >> k) & 1) cmulF(wr, wi, Afr[k], Afi[k]);
    }
    float sr = wr*Acr - wi*Aci;
    float si = wr*Aci + wi*Acr;
    #pragma unroll
    for (int d = 16; d >= 1; d >>= 1) {
        sr += __shfl_xor_sync(FULL, sr, d);
        si += __shfl_xor_sync(FULL, si, d);
    }
    if (lane == 0) g_tot[W] = make_float2(sr, si);
}

__global__ void __launch_bounds__(WPB * 32)
kA(const float* __restrict__ audio,
   const float* __restrict__ kre, const float* __restrict__ kim)
{
    if (blockIdx.x == NBLK) {               // table block for kC
        int c = threadIdx.x;
        if (c < CC) make_tab_double(kre, kim, c);
        return;
    }
    int lane = threadIdx.x & 31;
    int W = blockIdx.x * WPB + (threadIdx.x >> 5);
    int s = W / NSLICE;
    int j = W - s * NSLICE;
    int dir = s & 1, c = (s >> 1) & 63, b = s >> 7;

    const float* x = audio + (size_t)b * TT;
    if (dir == 0) sliceA<false>(x, j, lane, c, W, kre, kim);
    else          sliceA<true >(x, j, lane, c, W, kre, kim);
}

// ---------------- Kernel C: outputs ----------------
__device__ __forceinline__ void st_cs4(float* p, float4 v) {
    asm volatile("st.global.cs.v4.f32 [%0], {%1,%2,%3,%4};"
                 :: "l"(p), "f"(v.x), "f"(v.y), "f"(v.z), "f"(v.w) : "memory");
}

template <bool REV>
__device__ __forceinline__ void sliceC(const float* __restrict__ x,
                                       float* __restrict__ out_re,
                                       float* __restrict__ out_im,
                                       int s, int j, int lane,
                                       const float* __restrict__ tb)
{
    const unsigned FULL = 0xFFFFFFFFu;
    const float er  = tb[0],  eic = tb[1];
    const float a0r = tb[8],  a0i = tb[9];
    const float a1r = tb[10], a1i = tb[11];
    const float a2r = tb[12], a2i = tb[13];
    const float a3r = tb[14], a3i = tb[15];
    const float a4r = tb[16], a4i = tb[17];
    const float e128r = tb[18], e128i = tb[19];
    const float f19r  = tb[20], f19i  = tb[21];
    const float gr = tb[22], gi = tb[23];

    // packed recon constants: e^k as [ekr,ekr] and [-eki,+eki], k=1..4
    const unsigned long long e1rr = pk2(tb[0],  tb[0]),  e1in = pk2(-tb[1], tb[1]);
    const unsigned long long e2rr = pk2(tb[2],  tb[2]),  e2in = pk2(-tb[3], tb[3]);
    const unsigned long long e3rr = pk2(tb[4],  tb[4]),  e3in = pk2(-tb[5], tb[5]);
    const unsigned long long e4rr = pk2(tb[6],  tb[6]),  e4in = pk2(-tb[7], tb[7]);

    // q = E4^lane
    float qr = 1.f, qi = 0.f;
    #pragma unroll
    for (int k = 0; k < 5; ++k)
        if ((lane >> k) & 1) {
            float ar = tb[8 + 2*k], ai = tb[9 + 2*k];
            float nr = qr*ar - qi*ai, ni = qr*ai + qi*ar;
            qr = nr; qi = ni;
        }

    // fold predecessor slice totals -> entry state (uniform loads, all lanes)
    float inr = 0.f, ini = 0.f;
    const float2* tot = &g_tot[s * NSLICE];
    for (int t = 0; t < j; ++t) {
        float2 v = tot[t];
        float nr = v.x + f19r*inr - f19i*ini;
        float ni = v.y + f19r*ini + f19i*inr;
        inr = nr; ini = ni;
    }

    #pragma unroll 3
    for (int i = 0; i < NITERS; ++i) {
        int n0 = j * SLEN + i * 128 + lane * 4;
        float4 v = REV ? *reinterpret_cast<const float4*>(x + (TT - 4 - n0))
                       : *reinterpret_cast<const float4*>(x + n0);
        float x0, x1, x2, x3;
        if (!REV) { x0=v.x; x1=v.y; x2=v.z; x3=v.w; }
        else      { x0=v.w; x1=v.z; x2=v.y; x3=v.x; }

        // local partials from zero (kept for output reconstruction)
        float c1r = gr*x0, c1i = gi*x0;
        float c2r = er*c1r - eic*c1i + gr*x1, c2i = er*c1i + eic*c1r + gi*x1;
        float c3r = er*c2r - eic*c2i + gr*x2, c3i = er*c2i + eic*c2r + gi*x2;
        float c4r = er*c3r - eic*c3i + gr*x3, c4i = er*c3i + eic*c3r + gi*x3;

        // warp inclusive scan of c4 with ratio E4
        float sr = c4r, si = c4i;
        { float ur=__shfl_up_sync(FULL,sr,1),  ui=__shfl_up_sync(FULL,si,1);
          if (lane>=1)  { sr += a0r*ur - a0i*ui; si += a0r*ui + a0i*ur; } }
        { float ur=__shfl_up_sync(FULL,sr,2),  ui=__shfl_up_sync(FULL,si,2);
          if (lane>=2)  { sr += a1r*ur - a1i*ui; si += a1r*ui + a1i*ur; } }
        { float ur=__shfl_up_sync(FULL,sr,4),  ui=__shfl_up_sync(FULL,si,4);
          if (lane>=4)  { sr += a2r*ur - a2i*ui; si += a2r*ui + a2i*ur; } }
        { float ur=__shfl_up_sync(FULL,sr,8),  ui=__shfl_up_sync(FULL,si,8);
          if (lane>=8)  { sr += a3r*ur - a3i*ui; si += a3r*ui + a3i*ur; } }
        { float ur=__shfl_up_sync(FULL,sr,16), ui=__shfl_up_sync(FULL,si,16);
          if (lane>=16) { sr += a4r*ur - a4i*ui; si += a4r*ui + a4i*ur; } }

        float hr = __shfl_up_sync(FULL, sr, 1);
        float hi = __shfl_up_sync(FULL, si, 1);
        if (lane == 0) { hr = 0.f; hi = 0.f; }

        // lane entry z = h + q*in
        float zr = hr + qr*inr - qi*ini;
        float zi = hi + qr*ini + qi*inr;

        // packed reconstruction: o_k = c_k + e^k (x) z   (2 FFMA2 each)
        unsigned long long zP = pk2(zr, zi);
        unsigned long long zS = pk2(zi, zr);
        unsigned long long o1P = ffma2(e1in, zS, ffma2(e1rr, zP, pk2(c1r, c1i)));
        unsigned long long o2P = ffma2(e2in, zS, ffma2(e2rr, zP, pk2(c2r, c2i)));
        unsigned long long o3P = ffma2(e3in, zS, ffma2(e3rr, zP, pk2(c3r, c3i)));
        unsigned long long o4P = ffma2(e4in, zS, ffma2(e4rr, zP, pk2(c4r, c4i)));
        float o1r, o1i, o2r, o2i, o3r, o3i, o4r, o4i;
        unpk2(o1P, o1r, o1i);
        unpk2(o2P, o2r, o2i);
        unpk2(o3P, o3r, o3i);
        unpk2(o4P, o4r, o4i);

        if (!REV) {
            st_cs4(out_re + n0, make_float4(o1r,o2r,o3r,o4r));
            st_cs4(out_im + n0, make_float4(o1i,o2i,o3i,o4i));
        } else {
            st_cs4(out_re + (TT - 4 - n0), make_float4(o4r,o3r,o2r,o1r));
            st_cs4(out_im + (TT - 4 - n0), make_float4(o4i,o3i,o2i,o1i));
        }

        // advance slice-entry state: in = T + E128*in  (T = inclusive total, lane 31)
        float Tr = __shfl_sync(FULL, sr, 31);
        float Ti = __shfl_sync(FULL, si, 31);
        float nr = Tr + e128r*inr - e128i*ini;
        float ni = Ti + e128r*ini + e128i*inr;
        inr = nr; ini = ni;
    }
}

__global__ void __launch_bounds__(WPB * 32, 4)
kC(const float* __restrict__ audio, float* __restrict__ out)
{
    int lane = threadIdx.x & 31;
    int W = blockIdx.x * WPB + (threadIdx.x >> 5);
    int s = W / NSLICE;
    int j = W - s * NSLICE;
    int dir = s & 1, c = (s >> 1) & 63, b = s >> 7;

    const float* tb = g_ctab[c];
    const float* x = audio + (size_t)b * TT;
    float* base = out + (size_t)b * 4 * CC * TT;

    if (dir == 0) {
        sliceC<false>(x, base + (size_t)c * TT, base + (size_t)(CC + c) * TT,
                      s, j, lane, tb);
    } else {
        sliceC<true >(x, base + (size_t)(2*CC + c) * TT, base + (size_t)(3*CC + c) * TT,
                      s, j, lane, tb);
    }
}

extern "C" void kernel_launch(void* const* d_in, const int* in_sizes, int n_in,
                              void* d_out, int out_size)
{
    const float* audio = (const float*)d_in[0];
    const float* kre   = (const float*)d_in[1];
    const float* kim   = (const float*)d_in[2];
    float* out = (float*)d_out;
    (void)in_sizes; (void)n_in; (void)out_size;

    kA<<<NBLK + 1, WPB * 32>>>(audio, kre, kim);
    kC<<<NBLK, WPB * 32>>>(audio, out);
}